// round 8
// baseline (speedup 1.0000x reference)
#include <cuda_runtime.h>
#include <math.h>
#include <mma.h>
using namespace nvcuda;

#define NMAX 50000
#define EMAX 800000
#define EPMAX (EMAX + NMAX)
#define FH 256
#define NHEADS 4
#define NBPART ((NMAX + 1023) / 1024)

// ---------------- scratch (device globals) ------------------------------------
__device__ float g_h[NMAX * FH];       // activation ping
__device__ float g_h2[NMAX * FH];      // activation pong (pre-aggregation h)
__device__ float g_as[NMAX * NHEADS];  // alpha_src per node
__device__ float g_ad[NMAX * NHEADS];  // alpha_dst per node
__device__ float g_w[EPMAX * NHEADS];  // normalized per-edge weights
__device__ int   g_off[NMAX + 1];
__device__ int   g_deg[NMAX];
__device__ int   g_cur[NMAX];
__device__ int   g_srcs[EPMAX];
__device__ int   g_part[NBPART];
__device__ int   g_ppre[NBPART];

__device__ __forceinline__ float lrelu(float x) { return x > 0.f ? x : 0.2f * x; }

// ---------------- CSR build ----------------------------------------------------
__global__ void k_zero(int n) {
    int i = blockIdx.x * blockDim.x + threadIdx.x;
    if (i < n) { g_deg[i] = 0; g_cur[i] = 0; }
}

__global__ void k_deg(const int* __restrict__ ei, int E, int n) {
    int i = blockIdx.x * blockDim.x + threadIdx.x;
    int tot = E + n;
    if (i < tot) {
        int dst = (i < E) ? ei[E + i] : (i - E);
        atomicAdd(&g_deg[dst], 1);
    }
}

__global__ __launch_bounds__(1024) void k_part(int n) {
    __shared__ int s[1024];
    int i = blockIdx.x * 1024 + threadIdx.x;
    s[threadIdx.x] = (i < n) ? g_deg[i] : 0;
    __syncthreads();
    for (int off = 512; off > 0; off >>= 1) {
        if (threadIdx.x < off) s[threadIdx.x] += s[threadIdx.x + off];
        __syncthreads();
    }
    if (threadIdx.x == 0) g_part[blockIdx.x] = s[0];
}

__global__ void k_scanp(int nb) {
    __shared__ int s[64];
    int tid = threadIdx.x;
    s[tid] = (tid < nb) ? g_part[tid] : 0;
    __syncthreads();
    for (int off = 1; off < 64; off <<= 1) {
        int t = (tid >= off) ? s[tid - off] : 0;
        __syncthreads();
        s[tid] += t;
        __syncthreads();
    }
    if (tid < nb) g_ppre[tid] = (tid == 0) ? 0 : s[tid - 1];
}

__global__ __launch_bounds__(1024) void k_offsets(int n) {
    __shared__ int s[1024];
    int b = blockIdx.x;
    int i = b * 1024 + threadIdx.x;
    int v = (i < n) ? g_deg[i] : 0;
    s[threadIdx.x] = v;
    __syncthreads();
    for (int off = 1; off < 1024; off <<= 1) {
        int t = (threadIdx.x >= off) ? s[threadIdx.x - off] : 0;
        __syncthreads();
        s[threadIdx.x] += t;
        __syncthreads();
    }
    if (i < n) g_off[i + 1] = g_ppre[b] + s[threadIdx.x];
    if (b == 0 && threadIdx.x == 0) g_off[0] = 0;
}

__global__ void k_scatter(const int* __restrict__ ei, int E, int n) {
    int i = blockIdx.x * blockDim.x + threadIdx.x;
    int tot = E + n;
    if (i < tot) {
        int src, dst;
        if (i < E) { src = ei[i]; dst = ei[E + i]; }
        else       { src = i - E; dst = src; }
        int pos = g_off[dst] + atomicAdd(&g_cur[dst], 1);
        g_srcs[pos] = src;
    }
}

// ---------------- GEMM, 64x64 tile, double-buffered smem, fused alpha ----------
__global__ __launch_bounds__(256) void k_gemm_tc(
    const float* __restrict__ A, const float* __restrict__ B, float* __restrict__ C,
    const float* __restrict__ aS, const float* __restrict__ aD,
    float* __restrict__ gas, float* __restrict__ gad,
    int M, int N, int K)
{
    // 2 x (As 64x36 + Bs 32x68) floats = 8960 floats = 35840 B
    __shared__ float smem[2 * 64 * 36 + 2 * 32 * 68];
    float* AsB[2] = { smem, smem + 64 * 36 };
    float* BsB[2] = { smem + 2 * 64 * 36, smem + 2 * 64 * 36 + 32 * 68 };
    float (*Cs)[68] = (float(*)[68])smem;   // epilogue alias (4352 floats)

    int tid = threadIdx.x;
    int warp = tid >> 5;
    int row0 = blockIdx.y * 64, col0 = blockIdx.x * 64;
    int wr = (warp & 3) * 16;
    int wc = (warp >> 2) * 32;

    wmma::fragment<wmma::accumulator, 16, 16, 8, float> c0, c1;
    wmma::fill_fragment(c0, 0.f);
    wmma::fill_fragment(c1, 0.f);

    float4 ra[2], rb[2];
    // per-thread staging coords
    int amRow = tid >> 3;                 // 0..31 (x2 via +32)
    int amK   = (tid & 7) * 4;
    int bkK   = tid >> 4;                 // 0..15 (x2 via +16)
    int bkN   = (tid & 15) * 4;

    auto ldg = [&](int k0) {
#pragma unroll
        for (int r = 0; r < 2; r++) {
            int m = amRow + r * 32;
            ra[r] = (row0 + m < M) ? *(const float4*)&A[(size_t)(row0 + m) * K + k0 + amK]
                                   : make_float4(0.f, 0.f, 0.f, 0.f);
        }
#pragma unroll
        for (int r = 0; r < 2; r++) {
            int kk = bkK + r * 16;
            rb[r] = *(const float4*)&B[(size_t)(k0 + kk) * N + col0 + bkN];
        }
    };
    auto sts = [&](float* Asb, float* Bsb) {
#pragma unroll
        for (int r = 0; r < 2; r++) {
            int m = amRow + r * 32;
            float* p = Asb + m * 36 + amK;
            p[0] = wmma::__float_to_tf32(ra[r].x);
            p[1] = wmma::__float_to_tf32(ra[r].y);
            p[2] = wmma::__float_to_tf32(ra[r].z);
            p[3] = wmma::__float_to_tf32(ra[r].w);
        }
#pragma unroll
        for (int r = 0; r < 2; r++) {
            int kk = bkK + r * 16;
            float* p = Bsb + kk * 68 + bkN;
            p[0] = wmma::__float_to_tf32(rb[r].x);
            p[1] = wmma::__float_to_tf32(rb[r].y);
            p[2] = wmma::__float_to_tf32(rb[r].z);
            p[3] = wmma::__float_to_tf32(rb[r].w);
        }
    };

    int nk = K >> 5;
    ldg(0);
    sts(AsB[0], BsB[0]);
    __syncthreads();

    for (int kt = 0; kt < nk; kt++) {
        int cur = kt & 1;
        if (kt + 1 < nk) ldg((kt + 1) * 32);     // overlap loads with MMAs
        float* Asb = AsB[cur];
        float* Bsb = BsB[cur];
#pragma unroll
        for (int kk = 0; kk < 32; kk += 8) {
            wmma::fragment<wmma::matrix_a, 16, 16, 8, wmma::precision::tf32, wmma::row_major> a;
            wmma::fragment<wmma::matrix_b, 16, 16, 8, wmma::precision::tf32, wmma::row_major> b0, b1;
            wmma::load_matrix_sync(a, Asb + wr * 36 + kk, 36);
            wmma::load_matrix_sync(b0, Bsb + kk * 68 + wc, 68);
            wmma::load_matrix_sync(b1, Bsb + kk * 68 + wc + 16, 68);
            wmma::mma_sync(c0, a, b0, c0);
            wmma::mma_sync(c1, a, b1, c1);
        }
        if (kt + 1 < nk) sts(AsB[cur ^ 1], BsB[cur ^ 1]);
        __syncthreads();
    }

    wmma::store_matrix_sync(&Cs[wr][wc], c0, 68, wmma::mem_row_major);
    wmma::store_matrix_sync(&Cs[wr][wc + 16], c1, 68, wmma::mem_row_major);
    __syncthreads();

    // write C
    for (int idx = tid; idx < 64 * 64; idx += 256) {
        int m = idx >> 6, nn = idx & 63;
        if (row0 + m < M) C[(size_t)(row0 + m) * N + col0 + nn] = Cs[m][nn];
    }

    // fused alpha: quad of threads per row reduces 64 cols
    {
        int r = tid >> 2;        // 0..63
        int q = tid & 3;         // 0..3
        float ps = 0.f, pd = 0.f;
#pragma unroll
        for (int c = 0; c < 16; c++) {
            float v = Cs[r][q * 16 + c];
            ps = fmaf(v, aS[col0 + q * 16 + c], ps);
            pd = fmaf(v, aD[col0 + q * 16 + c], pd);
        }
        ps += __shfl_down_sync(0xffffffffu, ps, 2);
        pd += __shfl_down_sync(0xffffffffu, pd, 2);
        ps += __shfl_down_sync(0xffffffffu, ps, 1);
        pd += __shfl_down_sync(0xffffffffu, pd, 1);
        if (q == 0 && row0 + r < M) {
            int nh = N >> 6;
            int head = col0 >> 6;
            gas[(row0 + r) * nh + head] = ps;
            gad[(row0 + r) * nh + head] = pd;
        }
    }
}

// ---------------- per-edge weight precompute (warp per node) -------------------
__global__ __launch_bounds__(256) void k_wprep4(
    const float* __restrict__ as, const float* __restrict__ ad, int n)
{
    int warp = threadIdx.x >> 5, lane = threadIdx.x & 31;
    int node = blockIdx.x * 8 + warp;
    if (node >= n) return;
    int beg = g_off[node];
    int deg = g_off[node + 1] - beg;
    float4 adv = *(const float4*)(ad + node * 4);

    float m0 = -1e30f, m1 = -1e30f, m2 = -1e30f, m3 = -1e30f;
    for (int i = lane; i < deg; i += 32) {
        int s = g_srcs[beg + i];
        float4 av = *(const float4*)(as + s * 4);
        m0 = fmaxf(m0, lrelu(av.x + adv.x));
        m1 = fmaxf(m1, lrelu(av.y + adv.y));
        m2 = fmaxf(m2, lrelu(av.z + adv.z));
        m3 = fmaxf(m3, lrelu(av.w + adv.w));
    }
#pragma unroll
    for (int o = 16; o > 0; o >>= 1) {
        m0 = fmaxf(m0, __shfl_xor_sync(0xffffffffu, m0, o));
        m1 = fmaxf(m1, __shfl_xor_sync(0xffffffffu, m1, o));
        m2 = fmaxf(m2, __shfl_xor_sync(0xffffffffu, m2, o));
        m3 = fmaxf(m3, __shfl_xor_sync(0xffffffffu, m3, o));
    }
    float d0 = 0, d1 = 0, d2 = 0, d3 = 0;
    for (int i = lane; i < deg; i += 32) {
        int s = g_srcs[beg + i];
        float4 av = *(const float4*)(as + s * 4);
        float w0 = __expf(lrelu(av.x + adv.x) - m0);
        float w1 = __expf(lrelu(av.y + adv.y) - m1);
        float w2 = __expf(lrelu(av.z + adv.z) - m2);
        float w3 = __expf(lrelu(av.w + adv.w) - m3);
        *(float4*)(g_w + (size_t)(beg + i) * 4) = make_float4(w0, w1, w2, w3);
        d0 += w0; d1 += w1; d2 += w2; d3 += w3;
    }
#pragma unroll
    for (int o = 16; o > 0; o >>= 1) {
        d0 += __shfl_xor_sync(0xffffffffu, d0, o);
        d1 += __shfl_xor_sync(0xffffffffu, d1, o);
        d2 += __shfl_xor_sync(0xffffffffu, d2, o);
        d3 += __shfl_xor_sync(0xffffffffu, d3, o);
    }
    float r0 = 1.f / (d0 + 1e-16f);
    float r1 = 1.f / (d1 + 1e-16f);
    float r2 = 1.f / (d2 + 1e-16f);
    float r3 = 1.f / (d3 + 1e-16f);
    for (int i = lane; i < deg; i += 32) {
        float4 w = *(const float4*)(g_w + (size_t)(beg + i) * 4);
        w.x *= r0; w.y *= r1; w.z *= r2; w.w *= r3;
        *(float4*)(g_w + (size_t)(beg + i) * 4) = w;
    }
}

__global__ __launch_bounds__(256) void k_wprep1(
    const float* __restrict__ as, const float* __restrict__ ad, int n)
{
    int warp = threadIdx.x >> 5, lane = threadIdx.x & 31;
    int node = blockIdx.x * 8 + warp;
    if (node >= n) return;
    int beg = g_off[node];
    int deg = g_off[node + 1] - beg;
    float adv = ad[node];

    float m = -1e30f;
    for (int i = lane; i < deg; i += 32)
        m = fmaxf(m, lrelu(as[g_srcs[beg + i]] + adv));
#pragma unroll
    for (int o = 16; o > 0; o >>= 1)
        m = fmaxf(m, __shfl_xor_sync(0xffffffffu, m, o));
    float d = 0.f;
    for (int i = lane; i < deg; i += 32) {
        float w = __expf(lrelu(as[g_srcs[beg + i]] + adv) - m);
        g_w[beg + i] = w;
        d += w;
    }
#pragma unroll
    for (int o = 16; o > 0; o >>= 1)
        d += __shfl_xor_sync(0xffffffffu, d, o);
    float r = 1.f / (d + 1e-16f);
    for (int i = lane; i < deg; i += 32)
        g_w[beg + i] *= r;
}

// ---------------- GAT aggregation, H=4: 1 node/block, 256 thr, float4 ----------
__global__ __launch_bounds__(256) void k_agg4(
    const float* __restrict__ h, const float* __restrict__ bias,
    float* __restrict__ out, int elu)
{
    __shared__ float4 red[256];
    int n = blockIdx.x, tid = threadIdx.x;
    int sub = tid >> 6;           // edge subgroup 0..3
    int l   = tid & 63;           // feature quad: features 4l..4l+3
    int head = l >> 4;
    int beg = g_off[n];
    int deg = g_off[n + 1] - beg;

    float4 acc = make_float4(0.f, 0.f, 0.f, 0.f);
    int i = sub;
    for (; i + 4 < deg; i += 8) {
        int s0 = g_srcs[beg + i];
        int s1 = g_srcs[beg + i + 4];
        float w0 = g_w[(size_t)(beg + i) * 4 + head];
        float w1 = g_w[(size_t)(beg + i + 4) * 4 + head];
        float4 v0 = *(const float4*)&h[(size_t)s0 * 256 + l * 4];
        float4 v1 = *(const float4*)&h[(size_t)s1 * 256 + l * 4];
        acc.x = fmaf(v0.x, w0, acc.x); acc.y = fmaf(v0.y, w0, acc.y);
        acc.z = fmaf(v0.z, w0, acc.z); acc.w = fmaf(v0.w, w0, acc.w);
        acc.x = fmaf(v1.x, w1, acc.x); acc.y = fmaf(v1.y, w1, acc.y);
        acc.z = fmaf(v1.z, w1, acc.z); acc.w = fmaf(v1.w, w1, acc.w);
    }
    if (i < deg) {
        int s = g_srcs[beg + i];
        float w = g_w[(size_t)(beg + i) * 4 + head];
        float4 v = *(const float4*)&h[(size_t)s * 256 + l * 4];
        acc.x = fmaf(v.x, w, acc.x); acc.y = fmaf(v.y, w, acc.y);
        acc.z = fmaf(v.z, w, acc.z); acc.w = fmaf(v.w, w, acc.w);
    }

    red[tid] = acc;
    __syncthreads();
    if (sub == 0) {
        float4 a1 = red[l + 64], a2 = red[l + 128], a3 = red[l + 192];
        acc.x += a1.x + a2.x + a3.x;
        acc.y += a1.y + a2.y + a3.y;
        acc.z += a1.z + a2.z + a3.z;
        acc.w += a1.w + a2.w + a3.w;
        float4 b = *(const float4*)&bias[l * 4];
        acc.x += b.x; acc.y += b.y; acc.z += b.z; acc.w += b.w;
        if (elu) {
            acc.x = acc.x > 0.f ? acc.x : expm1f(acc.x);
            acc.y = acc.y > 0.f ? acc.y : expm1f(acc.y);
            acc.z = acc.z > 0.f ? acc.z : expm1f(acc.z);
            acc.w = acc.w > 0.f ? acc.w : expm1f(acc.w);
        }
        *(float4*)&out[(size_t)n * 256 + l * 4] = acc;
    }
}

// ---------------- GAT aggregation, H=1: 1 node/block, 64 thr, float4 -----------
// 4 edge-subgroups x 16 feature-lanes; smem reduce.
__global__ __launch_bounds__(64) void k_agg1(
    const float* __restrict__ h, const float* __restrict__ bias,
    float* __restrict__ out)
{
    __shared__ float4 red[64];
    int n = blockIdx.x, tid = threadIdx.x;
    int sub = tid >> 4;           // 0..3
    int l   = tid & 15;           // feature quad: features 4l..4l+3
    int beg = g_off[n];
    int deg = g_off[n + 1] - beg;

    float4 acc = make_float4(0.f, 0.f, 0.f, 0.f);
    int i = sub;
    for (; i + 4 < deg; i += 8) {
        int s0 = g_srcs[beg + i];
        int s1 = g_srcs[beg + i + 4];
        float w0 = g_w[beg + i];
        float w1 = g_w[beg + i + 4];
        float4 v0 = *(const float4*)&h[(size_t)s0 * 64 + l * 4];
        float4 v1 = *(const float4*)&h[(size_t)s1 * 64 + l * 4];
        acc.x = fmaf(v0.x, w0, acc.x); acc.y = fmaf(v0.y, w0, acc.y);
        acc.z = fmaf(v0.z, w0, acc.z); acc.w = fmaf(v0.w, w0, acc.w);
        acc.x = fmaf(v1.x, w1, acc.x); acc.y = fmaf(v1.y, w1, acc.y);
        acc.z = fmaf(v1.z, w1, acc.z); acc.w = fmaf(v1.w, w1, acc.w);
    }
    if (i < deg) {
        int s = g_srcs[beg + i];
        float w = g_w[beg + i];
        float4 v = *(const float4*)&h[(size_t)s * 64 + l * 4];
        acc.x = fmaf(v.x, w, acc.x); acc.y = fmaf(v.y, w, acc.y);
        acc.z = fmaf(v.z, w, acc.z); acc.w = fmaf(v.w, w, acc.w);
    }

    red[tid] = acc;
    __syncthreads();
    if (sub == 0) {
        float4 a1 = red[l + 16], a2 = red[l + 32], a3 = red[l + 48];
        acc.x += a1.x + a2.x + a3.x;
        acc.y += a1.y + a2.y + a3.y;
        acc.z += a1.z + a2.z + a3.z;
        acc.w += a1.w + a2.w + a3.w;
        float4 b = *(const float4*)&bias[l * 4];
        acc.x += b.x; acc.y += b.y; acc.z += b.z; acc.w += b.w;
        *(float4*)&out[(size_t)n * 64 + l * 4] = acc;
    }
}

// ---------------- mean pool over sorted batch ids -----------------------------
__global__ void k_pool(const float* __restrict__ node, const int* __restrict__ batch,
                       float* __restrict__ gout, int n)
{
    int g = blockIdx.x;
    int lo = 0, hi = n;
    while (lo < hi) { int mid = (lo + hi) >> 1; if (batch[mid] < g) lo = mid + 1; else hi = mid; }
    int start = lo;
    lo = start; hi = n;
    while (lo < hi) { int mid = (lo + hi) >> 1; if (batch[mid] < g + 1) lo = mid + 1; else hi = mid; }
    int end = lo;

    int f = threadIdx.x & 63;
    int sub = threadIdx.x >> 6;
    float acc = 0.f;
    for (int i = start + sub; i < end; i += 4)
        acc += node[(size_t)i * 64 + f];
    __shared__ float s[256];
    s[threadIdx.x] = acc;
    __syncthreads();
    if (threadIdx.x < 64) {
        float v = s[threadIdx.x] + s[threadIdx.x + 64] + s[threadIdx.x + 128] + s[threadIdx.x + 192];
        int cnt = end - start;
        gout[g * 64 + threadIdx.x] = v / (float)max(cnt, 1);
    }
}

// ---------------- host side ----------------------------------------------------
extern "C" void kernel_launch(void* const* d_in, const int* in_sizes, int n_in,
                              void* d_out, int out_size)
{
    const float* x    = (const float*)d_in[0];
    const int*   ei   = (const int*)d_in[1];
    const int*   batch= (const int*)d_in[2];
    const float* W1   = (const float*)d_in[3];
    const float* as1  = (const float*)d_in[4];
    const float* ad1  = (const float*)d_in[5];
    const float* b1   = (const float*)d_in[6];
    const float* W2   = (const float*)d_in[7];
    const float* as2  = (const float*)d_in[8];
    const float* ad2  = (const float*)d_in[9];
    const float* b2   = (const float*)d_in[10];
    const float* W3   = (const float*)d_in[11];
    const float* as3  = (const float*)d_in[12];
    const float* ad3  = (const float*)d_in[13];
    const float* b3   = (const float*)d_in[14];

    int n = in_sizes[0] / 256;
    int E = in_sizes[1] / 2;
    float* out = (float*)d_out;
    int G = (out_size - n * 64) / 64;

    float *p_h, *p_h2, *p_as, *p_ad;
    cudaGetSymbolAddress((void**)&p_h,  g_h);
    cudaGetSymbolAddress((void**)&p_h2, g_h2);
    cudaGetSymbolAddress((void**)&p_as, g_as);
    cudaGetSymbolAddress((void**)&p_ad, g_ad);

    int tot = E + n;
    int nb = (n + 1023) / 1024;
    int nw = (n + 7) / 8;

    dim3 gbig(256 / 64, (n + 63) / 64);
    dim3 gsm(1, (n + 63) / 64);

    k_zero<<<(n + 255) / 256, 256>>>(n);
    k_deg<<<(tot + 255) / 256, 256>>>(ei, E, n);
    k_part<<<nb, 1024>>>(n);
    k_scanp<<<1, 64>>>(nb);
    k_offsets<<<nb, 1024>>>(n);
    k_gemm_tc<<<gbig, 256>>>(x, W1, p_h2, as1, ad1, p_as, p_ad, n, 256, 256);
    k_scatter<<<(tot + 255) / 256, 256>>>(ei, E, n);

    // layer 1 (cont.)
    k_wprep4<<<nw, 256>>>(p_as, p_ad, n);
    k_agg4<<<n, 256>>>(p_h2, b1, p_h, 1);
    // layer 2
    k_gemm_tc<<<gbig, 256>>>(p_h, W2, p_h2, as2, ad2, p_as, p_ad, n, 256, 256);
    k_wprep4<<<nw, 256>>>(p_as, p_ad, n);
    k_agg4<<<n, 256>>>(p_h2, b2, p_h, 1);
    // layer 3
    k_gemm_tc<<<gsm, 256>>>(p_h, W3, p_h2, as3, ad3, p_as, p_ad, n, 64, 256);
    k_wprep1<<<nw, 256>>>(p_as, p_ad, n);
    k_agg1<<<n, 64>>>(p_h2, b3, out);
    // pooling
    k_pool<<<G, 256>>>(out, batch, out + n * 64, n);
}

// round 9
// speedup vs baseline: 1.1792x; 1.1792x over previous
#include <cuda_runtime.h>
#include <math.h>
#include <mma.h>
using namespace nvcuda;

#define NMAX 50000
#define EMAX 800000
#define EPMAX (EMAX + NMAX)
#define FH 256
#define NHEADS 4
#define NBPART ((NMAX + 1023) / 1024)

// ---------------- scratch (device globals) ------------------------------------
__device__ float g_h[NMAX * FH];       // activation ping
__device__ float g_h2[NMAX * FH];      // activation pong (pre-aggregation h)
__device__ float g_as[NMAX * NHEADS];  // alpha_src per node
__device__ float g_ad[NMAX * NHEADS];  // alpha_dst per node
__device__ float g_w[EPMAX * NHEADS];  // normalized per-edge weights
__device__ int   g_off[NMAX + 1];
__device__ int   g_deg[NMAX];
__device__ int   g_cur[NMAX];
__device__ int   g_srcs[EPMAX];
__device__ int   g_part[NBPART];
__device__ int   g_ppre[NBPART];

__device__ __forceinline__ float lrelu(float x) { return x > 0.f ? x : 0.2f * x; }

// ---------------- CSR build ----------------------------------------------------
__global__ void k_zero(int n) {
    int i = blockIdx.x * blockDim.x + threadIdx.x;
    if (i < n) { g_deg[i] = 0; g_cur[i] = 0; }
}

__global__ void k_deg(const int* __restrict__ ei, int E, int n) {
    int i = blockIdx.x * blockDim.x + threadIdx.x;
    int tot = E + n;
    if (i < tot) {
        int dst = (i < E) ? ei[E + i] : (i - E);
        atomicAdd(&g_deg[dst], 1);
    }
}

__global__ __launch_bounds__(1024) void k_part(int n) {
    __shared__ int s[1024];
    int i = blockIdx.x * 1024 + threadIdx.x;
    s[threadIdx.x] = (i < n) ? g_deg[i] : 0;
    __syncthreads();
    for (int off = 512; off > 0; off >>= 1) {
        if (threadIdx.x < off) s[threadIdx.x] += s[threadIdx.x + off];
        __syncthreads();
    }
    if (threadIdx.x == 0) g_part[blockIdx.x] = s[0];
}

__global__ void k_scanp(int nb) {
    __shared__ int s[64];
    int tid = threadIdx.x;
    s[tid] = (tid < nb) ? g_part[tid] : 0;
    __syncthreads();
    for (int off = 1; off < 64; off <<= 1) {
        int t = (tid >= off) ? s[tid - off] : 0;
        __syncthreads();
        s[tid] += t;
        __syncthreads();
    }
    if (tid < nb) g_ppre[tid] = (tid == 0) ? 0 : s[tid - 1];
}

__global__ __launch_bounds__(1024) void k_offsets(int n) {
    __shared__ int s[1024];
    int b = blockIdx.x;
    int i = b * 1024 + threadIdx.x;
    int v = (i < n) ? g_deg[i] : 0;
    s[threadIdx.x] = v;
    __syncthreads();
    for (int off = 1; off < 1024; off <<= 1) {
        int t = (threadIdx.x >= off) ? s[threadIdx.x - off] : 0;
        __syncthreads();
        s[threadIdx.x] += t;
        __syncthreads();
    }
    if (i < n) g_off[i + 1] = g_ppre[b] + s[threadIdx.x];
    if (b == 0 && threadIdx.x == 0) g_off[0] = 0;
}

__global__ void k_scatter(const int* __restrict__ ei, int E, int n) {
    int i = blockIdx.x * blockDim.x + threadIdx.x;
    int tot = E + n;
    if (i < tot) {
        int src, dst;
        if (i < E) { src = ei[i]; dst = ei[E + i]; }
        else       { src = i - E; dst = src; }
        int pos = g_off[dst] + atomicAdd(&g_cur[dst], 1);
        g_srcs[pos] = src;
    }
}

// ---------------- GEMM + fused alpha epilogue (64x64 tiles, R7-proven) ---------
__global__ __launch_bounds__(256) void k_gemm_tc(
    const float* __restrict__ A, const float* __restrict__ B, float* __restrict__ C,
    const float* __restrict__ aS, const float* __restrict__ aD,
    float* __restrict__ gas, float* __restrict__ gad,
    int M, int N, int K)
{
    __shared__ float As[64][36];
    __shared__ float Bs[32][68];
    __shared__ float Cs[64][68];

    int tid = threadIdx.x;
    int warp = tid >> 5;
    int row0 = blockIdx.y * 64, col0 = blockIdx.x * 64;
    int wr = (warp & 3) * 16;
    int wc = (warp >> 2) * 32;

    wmma::fragment<wmma::accumulator, 16, 16, 8, float> c0, c1;
    wmma::fill_fragment(c0, 0.f);
    wmma::fill_fragment(c1, 0.f);

    for (int k0 = 0; k0 < K; k0 += 32) {
#pragma unroll
        for (int r = 0; r < 2; r++) {
            int idx = tid + r * 256;
            int m = idx >> 3;
            int kk = (idx & 7) * 4;
            float4 v = make_float4(0.f, 0.f, 0.f, 0.f);
            if (row0 + m < M) v = *(const float4*)&A[(size_t)(row0 + m) * K + k0 + kk];
            As[m][kk + 0] = wmma::__float_to_tf32(v.x);
            As[m][kk + 1] = wmma::__float_to_tf32(v.y);
            As[m][kk + 2] = wmma::__float_to_tf32(v.z);
            As[m][kk + 3] = wmma::__float_to_tf32(v.w);
        }
#pragma unroll
        for (int r = 0; r < 2; r++) {
            int idx = tid + r * 256;
            int kk = idx >> 4;
            int nn = (idx & 15) * 4;
            float4 v = *(const float4*)&B[(size_t)(k0 + kk) * N + col0 + nn];
            Bs[kk][nn + 0] = wmma::__float_to_tf32(v.x);
            Bs[kk][nn + 1] = wmma::__float_to_tf32(v.y);
            Bs[kk][nn + 2] = wmma::__float_to_tf32(v.z);
            Bs[kk][nn + 3] = wmma::__float_to_tf32(v.w);
        }
        __syncthreads();
#pragma unroll
        for (int kk = 0; kk < 32; kk += 8) {
            wmma::fragment<wmma::matrix_a, 16, 16, 8, wmma::precision::tf32, wmma::row_major> a;
            wmma::fragment<wmma::matrix_b, 16, 16, 8, wmma::precision::tf32, wmma::row_major> b0, b1;
            wmma::load_matrix_sync(a, &As[wr][kk], 36);
            wmma::load_matrix_sync(b0, &Bs[kk][wc], 68);
            wmma::load_matrix_sync(b1, &Bs[kk][wc + 16], 68);
            wmma::mma_sync(c0, a, b0, c0);
            wmma::mma_sync(c1, a, b1, c1);
        }
        __syncthreads();
    }

    wmma::store_matrix_sync(&Cs[wr][wc], c0, 68, wmma::mem_row_major);
    wmma::store_matrix_sync(&Cs[wr][wc + 16], c1, 68, wmma::mem_row_major);
    __syncthreads();

    // write C
    for (int idx = tid; idx < 64 * 64; idx += 256) {
        int m = idx >> 6, nn = idx & 63;
        if (row0 + m < M) C[(size_t)(row0 + m) * N + col0 + nn] = Cs[m][nn];
    }

    // fused alpha: quad of threads per row reduces 64 cols
    {
        int r = tid >> 2;        // 0..63
        int q = tid & 3;         // 0..3
        float ps = 0.f, pd = 0.f;
#pragma unroll
        for (int c = 0; c < 16; c++) {
            float v = Cs[r][q * 16 + c];
            ps = fmaf(v, aS[col0 + q * 16 + c], ps);
            pd = fmaf(v, aD[col0 + q * 16 + c], pd);
        }
        ps += __shfl_down_sync(0xffffffffu, ps, 2);
        pd += __shfl_down_sync(0xffffffffu, pd, 2);
        ps += __shfl_down_sync(0xffffffffu, ps, 1);
        pd += __shfl_down_sync(0xffffffffu, pd, 1);
        if (q == 0 && row0 + r < M) {
            int nh = N >> 6;
            int head = col0 >> 6;
            gas[(row0 + r) * nh + head] = ps;
            gad[(row0 + r) * nh + head] = pd;
        }
    }
}

// ---------------- per-edge weight precompute (warp per node) -------------------
__global__ __launch_bounds__(256) void k_wprep4(
    const float* __restrict__ as, const float* __restrict__ ad, int n)
{
    int warp = threadIdx.x >> 5, lane = threadIdx.x & 31;
    int node = blockIdx.x * 8 + warp;
    if (node >= n) return;
    int beg = g_off[node];
    int deg = g_off[node + 1] - beg;
    float4 adv = *(const float4*)(ad + node * 4);

    float m0 = -1e30f, m1 = -1e30f, m2 = -1e30f, m3 = -1e30f;
    for (int i = lane; i < deg; i += 32) {
        int s = g_srcs[beg + i];
        float4 av = *(const float4*)(as + s * 4);
        m0 = fmaxf(m0, lrelu(av.x + adv.x));
        m1 = fmaxf(m1, lrelu(av.y + adv.y));
        m2 = fmaxf(m2, lrelu(av.z + adv.z));
        m3 = fmaxf(m3, lrelu(av.w + adv.w));
    }
#pragma unroll
    for (int o = 16; o > 0; o >>= 1) {
        m0 = fmaxf(m0, __shfl_xor_sync(0xffffffffu, m0, o));
        m1 = fmaxf(m1, __shfl_xor_sync(0xffffffffu, m1, o));
        m2 = fmaxf(m2, __shfl_xor_sync(0xffffffffu, m2, o));
        m3 = fmaxf(m3, __shfl_xor_sync(0xffffffffu, m3, o));
    }
    float d0 = 0, d1 = 0, d2 = 0, d3 = 0;
    for (int i = lane; i < deg; i += 32) {
        int s = g_srcs[beg + i];
        float4 av = *(const float4*)(as + s * 4);
        float w0 = __expf(lrelu(av.x + adv.x) - m0);
        float w1 = __expf(lrelu(av.y + adv.y) - m1);
        float w2 = __expf(lrelu(av.z + adv.z) - m2);
        float w3 = __expf(lrelu(av.w + adv.w) - m3);
        *(float4*)(g_w + (size_t)(beg + i) * 4) = make_float4(w0, w1, w2, w3);
        d0 += w0; d1 += w1; d2 += w2; d3 += w3;
    }
#pragma unroll
    for (int o = 16; o > 0; o >>= 1) {
        d0 += __shfl_xor_sync(0xffffffffu, d0, o);
        d1 += __shfl_xor_sync(0xffffffffu, d1, o);
        d2 += __shfl_xor_sync(0xffffffffu, d2, o);
        d3 += __shfl_xor_sync(0xffffffffu, d3, o);
    }
    float r0 = 1.f / (d0 + 1e-16f);
    float r1 = 1.f / (d1 + 1e-16f);
    float r2 = 1.f / (d2 + 1e-16f);
    float r3 = 1.f / (d3 + 1e-16f);
    for (int i = lane; i < deg; i += 32) {
        float4 w = *(const float4*)(g_w + (size_t)(beg + i) * 4);
        w.x *= r0; w.y *= r1; w.z *= r2; w.w *= r3;
        *(float4*)(g_w + (size_t)(beg + i) * 4) = w;
    }
}

__global__ __launch_bounds__(256) void k_wprep1(
    const float* __restrict__ as, const float* __restrict__ ad, int n)
{
    int warp = threadIdx.x >> 5, lane = threadIdx.x & 31;
    int node = blockIdx.x * 8 + warp;
    if (node >= n) return;
    int beg = g_off[node];
    int deg = g_off[node + 1] - beg;
    float adv = ad[node];

    float m = -1e30f;
    for (int i = lane; i < deg; i += 32)
        m = fmaxf(m, lrelu(as[g_srcs[beg + i]] + adv));
#pragma unroll
    for (int o = 16; o > 0; o >>= 1)
        m = fmaxf(m, __shfl_xor_sync(0xffffffffu, m, o));
    float d = 0.f;
    for (int i = lane; i < deg; i += 32) {
        float w = __expf(lrelu(as[g_srcs[beg + i]] + adv) - m);
        g_w[beg + i] = w;
        d += w;
    }
#pragma unroll
    for (int o = 16; o > 0; o >>= 1)
        d += __shfl_xor_sync(0xffffffffu, d, o);
    float r = 1.f / (d + 1e-16f);
    for (int i = lane; i < deg; i += 32)
        g_w[beg + i] *= r;
}

// ---------------- GAT aggregation, H=4: 1 node/block, 256 thr, float4 ----------
__global__ __launch_bounds__(256) void k_agg4(
    const float* __restrict__ h, const float* __restrict__ bias,
    float* __restrict__ out, int elu)
{
    __shared__ float4 red[256];
    int n = blockIdx.x, tid = threadIdx.x;
    int sub = tid >> 6;           // edge subgroup 0..3
    int l   = tid & 63;           // feature quad: features 4l..4l+3
    int head = l >> 4;
    int beg = g_off[n];
    int deg = g_off[n + 1] - beg;

    float4 acc = make_float4(0.f, 0.f, 0.f, 0.f);
    int i = sub;
    for (; i + 4 < deg; i += 8) {
        int s0 = g_srcs[beg + i];
        int s1 = g_srcs[beg + i + 4];
        float w0 = g_w[(size_t)(beg + i) * 4 + head];
        float w1 = g_w[(size_t)(beg + i + 4) * 4 + head];
        float4 v0 = *(const float4*)&h[(size_t)s0 * 256 + l * 4];
        float4 v1 = *(const float4*)&h[(size_t)s1 * 256 + l * 4];
        acc.x = fmaf(v0.x, w0, acc.x); acc.y = fmaf(v0.y, w0, acc.y);
        acc.z = fmaf(v0.z, w0, acc.z); acc.w = fmaf(v0.w, w0, acc.w);
        acc.x = fmaf(v1.x, w1, acc.x); acc.y = fmaf(v1.y, w1, acc.y);
        acc.z = fmaf(v1.z, w1, acc.z); acc.w = fmaf(v1.w, w1, acc.w);
    }
    if (i < deg) {
        int s = g_srcs[beg + i];
        float w = g_w[(size_t)(beg + i) * 4 + head];
        float4 v = *(const float4*)&h[(size_t)s * 256 + l * 4];
        acc.x = fmaf(v.x, w, acc.x); acc.y = fmaf(v.y, w, acc.y);
        acc.z = fmaf(v.z, w, acc.z); acc.w = fmaf(v.w, w, acc.w);
    }

    red[tid] = acc;
    __syncthreads();
    if (sub == 0) {
        float4 a1 = red[l + 64], a2 = red[l + 128], a3 = red[l + 192];
        acc.x += a1.x + a2.x + a3.x;
        acc.y += a1.y + a2.y + a3.y;
        acc.z += a1.z + a2.z + a3.z;
        acc.w += a1.w + a2.w + a3.w;
        float4 b = *(const float4*)&bias[l * 4];
        acc.x += b.x; acc.y += b.y; acc.z += b.z; acc.w += b.w;
        if (elu) {
            acc.x = acc.x > 0.f ? acc.x : expm1f(acc.x);
            acc.y = acc.y > 0.f ? acc.y : expm1f(acc.y);
            acc.z = acc.z > 0.f ? acc.z : expm1f(acc.z);
            acc.w = acc.w > 0.f ? acc.w : expm1f(acc.w);
        }
        *(float4*)&out[(size_t)n * 256 + l * 4] = acc;
    }
}

// ---------------- GAT aggregation, H=1, F=64 (R7-proven) -----------------------
__global__ __launch_bounds__(64) void k_agg1(
    const float* __restrict__ h, const float* __restrict__ bias,
    float* __restrict__ out)
{
    int n = blockIdx.x, f = threadIdx.x;
    int beg = g_off[n];
    int deg = g_off[n + 1] - beg;

    float acc = 0.f;
    int i = 0;
    for (; i + 4 <= deg; i += 4) {
        int s0 = g_srcs[beg + i + 0];
        int s1 = g_srcs[beg + i + 1];
        int s2 = g_srcs[beg + i + 2];
        int s3 = g_srcs[beg + i + 3];
        float w0 = g_w[beg + i + 0];
        float w1 = g_w[beg + i + 1];
        float w2 = g_w[beg + i + 2];
        float w3 = g_w[beg + i + 3];
        acc = fmaf(h[(size_t)s0 * 64 + f], w0, acc);
        acc = fmaf(h[(size_t)s1 * 64 + f], w1, acc);
        acc = fmaf(h[(size_t)s2 * 64 + f], w2, acc);
        acc = fmaf(h[(size_t)s3 * 64 + f], w3, acc);
    }
    for (; i < deg; i++)
        acc = fmaf(h[(size_t)g_srcs[beg + i] * 64 + f], g_w[beg + i], acc);
    out[(size_t)n * 64 + f] = acc + bias[f];
}

// ---------------- mean pool over sorted batch ids -----------------------------
__global__ void k_pool(const float* __restrict__ node, const int* __restrict__ batch,
                       float* __restrict__ gout, int n)
{
    int g = blockIdx.x;
    int lo = 0, hi = n;
    while (lo < hi) { int mid = (lo + hi) >> 1; if (batch[mid] < g) lo = mid + 1; else hi = mid; }
    int start = lo;
    lo = start; hi = n;
    while (lo < hi) { int mid = (lo + hi) >> 1; if (batch[mid] < g + 1) lo = mid + 1; else hi = mid; }
    int end = lo;

    int f = threadIdx.x & 63;
    int sub = threadIdx.x >> 6;
    float acc = 0.f;
    for (int i = start + sub; i < end; i += 4)
        acc += node[(size_t)i * 64 + f];
    __shared__ float s[256];
    s[threadIdx.x] = acc;
    __syncthreads();
    if (threadIdx.x < 64) {
        float v = s[threadIdx.x] + s[threadIdx.x + 64] + s[threadIdx.x + 128] + s[threadIdx.x + 192];
        int cnt = end - start;
        gout[g * 64 + threadIdx.x] = v / (float)max(cnt, 1);
    }
}

// ---------------- host side ----------------------------------------------------
extern "C" void kernel_launch(void* const* d_in, const int* in_sizes, int n_in,
                              void* d_out, int out_size)
{
    const float* x    = (const float*)d_in[0];
    const int*   ei   = (const int*)d_in[1];
    const int*   batch= (const int*)d_in[2];
    const float* W1   = (const float*)d_in[3];
    const float* as1  = (const float*)d_in[4];
    const float* ad1  = (const float*)d_in[5];
    const float* b1   = (const float*)d_in[6];
    const float* W2   = (const float*)d_in[7];
    const float* as2  = (const float*)d_in[8];
    const float* ad2  = (const float*)d_in[9];
    const float* b2   = (const float*)d_in[10];
    const float* W3   = (const float*)d_in[11];
    const float* as3  = (const float*)d_in[12];
    const float* ad3  = (const float*)d_in[13];
    const float* b3   = (const float*)d_in[14];

    int n = in_sizes[0] / 256;
    int E = in_sizes[1] / 2;
    float* out = (float*)d_out;
    int G = (out_size - n * 64) / 64;

    float *p_h, *p_h2, *p_as, *p_ad;
    cudaGetSymbolAddress((void**)&p_h,  g_h);
    cudaGetSymbolAddress((void**)&p_h2, g_h2);
    cudaGetSymbolAddress((void**)&p_as, g_as);
    cudaGetSymbolAddress((void**)&p_ad, g_ad);

    int tot = E + n;
    int nb = (n + 1023) / 1024;
    int nw = (n + 7) / 8;

    dim3 gbig(256 / 64, (n + 63) / 64);
    dim3 gsm(1, (n + 63) / 64);

    // Launch index 3 = layer-1 GEMM (independent of CSR chain) so the ncu
    // capture, which consistently profiles launch #3, lands on the dominant kernel.
    k_zero<<<(n + 255) / 256, 256>>>(n);                                        // 0
    k_deg<<<(tot + 255) / 256, 256>>>(ei, E, n);                                // 1
    k_part<<<nb, 1024>>>(n);                                                    // 2
    k_gemm_tc<<<gbig, 256>>>(x, W1, p_h2, as1, ad1, p_as, p_ad, n, 256, 256);   // 3
    k_scanp<<<1, 64>>>(nb);                                                     // 4
    k_offsets<<<nb, 1024>>>(n);                                                 // 5
    k_scatter<<<(tot + 255) / 256, 256>>>(ei, E, n);                            // 6

    // layer 1 (cont.)
    k_wprep4<<<nw, 256>>>(p_as, p_ad, n);
    k_agg4<<<n, 256>>>(p_h2, b1, p_h, 1);
    // layer 2
    k_gemm_tc<<<gbig, 256>>>(p_h, W2, p_h2, as2, ad2, p_as, p_ad, n, 256, 256);
    k_wprep4<<<nw, 256>>>(p_as, p_ad, n);
    k_agg4<<<n, 256>>>(p_h2, b2, p_h, 1);
    // layer 3
    k_gemm_tc<<<gsm, 256>>>(p_h, W3, p_h2, as3, ad3, p_as, p_ad, n, 64, 256);
    k_wprep1<<<nw, 256>>>(p_as, p_ad, n);
    k_agg1<<<n, 64>>>(p_h2, b3, out);
    // pooling
    k_pool<<<G, 256>>>(out, batch, out + n * 64, n);
}

// round 10
// speedup vs baseline: 1.2502x; 1.0602x over previous
#include <cuda_runtime.h>
#include <math.h>
#include <mma.h>
using namespace nvcuda;

#define NMAX 50000
#define EMAX 800000
#define EPMAX (EMAX + NMAX)
#define FH 256
#define NHEADS 4
#define NBPART ((NMAX + 1023) / 1024)

// ---------------- scratch (device globals) ------------------------------------
__device__ float g_h[NMAX * FH];       // activation ping
__device__ float g_h2[NMAX * FH];      // activation pong (pre-aggregation h)
__device__ float g_as[NMAX * NHEADS];  // alpha_src per node
__device__ float g_ad[NMAX * NHEADS];  // alpha_dst per node
__device__ float g_w[EPMAX * NHEADS];  // normalized per-edge weights
__device__ int   g_off[NMAX + 1];
__device__ int   g_deg[NMAX];
__device__ int   g_cur[NMAX];
__device__ int   g_srcs[EPMAX];
__device__ int   g_part[NBPART];
__device__ int   g_ppre[NBPART];

__device__ __forceinline__ float lrelu(float x) { return x > 0.f ? x : 0.2f * x; }

// ---------------- CSR build ----------------------------------------------------
__global__ void k_zero(int n) {
    int i = blockIdx.x * blockDim.x + threadIdx.x;
    if (i < n) { g_deg[i] = 0; g_cur[i] = 0; }
}

__global__ void k_deg(const int* __restrict__ ei, int E, int n) {
    int i = blockIdx.x * blockDim.x + threadIdx.x;
    int tot = E + n;
    if (i < tot) {
        int dst = (i < E) ? ei[E + i] : (i - E);
        atomicAdd(&g_deg[dst], 1);
    }
}

__global__ __launch_bounds__(1024) void k_part(int n) {
    __shared__ int s[1024];
    int i = blockIdx.x * 1024 + threadIdx.x;
    s[threadIdx.x] = (i < n) ? g_deg[i] : 0;
    __syncthreads();
    for (int off = 512; off > 0; off >>= 1) {
        if (threadIdx.x < off) s[threadIdx.x] += s[threadIdx.x + off];
        __syncthreads();
    }
    if (threadIdx.x == 0) g_part[blockIdx.x] = s[0];
}

__global__ void k_scanp(int nb) {
    __shared__ int s[64];
    int tid = threadIdx.x;
    s[tid] = (tid < nb) ? g_part[tid] : 0;
    __syncthreads();
    for (int off = 1; off < 64; off <<= 1) {
        int t = (tid >= off) ? s[tid - off] : 0;
        __syncthreads();
        s[tid] += t;
        __syncthreads();
    }
    if (tid < nb) g_ppre[tid] = (tid == 0) ? 0 : s[tid - 1];
}

__global__ __launch_bounds__(1024) void k_offsets(int n) {
    __shared__ int s[1024];
    int b = blockIdx.x;
    int i = b * 1024 + threadIdx.x;
    int v = (i < n) ? g_deg[i] : 0;
    s[threadIdx.x] = v;
    __syncthreads();
    for (int off = 1; off < 1024; off <<= 1) {
        int t = (threadIdx.x >= off) ? s[threadIdx.x - off] : 0;
        __syncthreads();
        s[threadIdx.x] += t;
        __syncthreads();
    }
    if (i < n) g_off[i + 1] = g_ppre[b] + s[threadIdx.x];
    if (b == 0 && threadIdx.x == 0) g_off[0] = 0;
}

__global__ void k_scatter(const int* __restrict__ ei, int E, int n) {
    int i = blockIdx.x * blockDim.x + threadIdx.x;
    int tot = E + n;
    if (i < tot) {
        int src, dst;
        if (i < E) { src = ei[i]; dst = ei[E + i]; }
        else       { src = i - E; dst = src; }
        int pos = g_off[dst] + atomicAdd(&g_cur[dst], 1);
        g_srcs[pos] = src;
    }
}

// ---------------- GEMM: 128x64 block tile, 8 warps x 32x32, fused alpha --------
// Simple load->sync->MMA->sync (no register staging across MMAs).
__global__ __launch_bounds__(256) void k_gemm_tc(
    const float* __restrict__ A, const float* __restrict__ B, float* __restrict__ C,
    const float* __restrict__ aS, const float* __restrict__ aD,
    float* __restrict__ gas, float* __restrict__ gad,
    int M, int N, int K)
{
    __shared__ float smem[128 * 68];                 // 34816 B
    float* As = smem;                                // [128][36] = 4608 floats
    float* Bs = smem + 128 * 36;                     // [32][68]  = 2176 floats
    float (*Cs)[68] = (float(*)[68])smem;            // epilogue alias [128][68]

    int tid = threadIdx.x;
    int warp = tid >> 5;
    int row0 = blockIdx.y * 128, col0 = blockIdx.x * 64;
    int wr = (warp & 3) * 32;
    int wc = (warp >> 2) * 32;

    wmma::fragment<wmma::accumulator, 16, 16, 8, float> c[2][2];
#pragma unroll
    for (int i = 0; i < 2; i++)
#pragma unroll
        for (int j = 0; j < 2; j++)
            wmma::fill_fragment(c[i][j], 0.f);

    for (int k0 = 0; k0 < K; k0 += 32) {
        // stage A 128x32
#pragma unroll
        for (int r = 0; r < 4; r++) {
            int idx = tid + r * 256;
            int m = idx >> 3;
            int kk = (idx & 7) * 4;
            float4 v = make_float4(0.f, 0.f, 0.f, 0.f);
            if (row0 + m < M) v = *(const float4*)&A[(size_t)(row0 + m) * K + k0 + kk];
            float* p = As + m * 36 + kk;
            p[0] = wmma::__float_to_tf32(v.x);
            p[1] = wmma::__float_to_tf32(v.y);
            p[2] = wmma::__float_to_tf32(v.z);
            p[3] = wmma::__float_to_tf32(v.w);
        }
        // stage B 32x64
#pragma unroll
        for (int r = 0; r < 2; r++) {
            int idx = tid + r * 256;
            int kk = idx >> 4;
            int nn = (idx & 15) * 4;
            float4 v = *(const float4*)&B[(size_t)(k0 + kk) * N + col0 + nn];
            float* p = Bs + kk * 68 + nn;
            p[0] = wmma::__float_to_tf32(v.x);
            p[1] = wmma::__float_to_tf32(v.y);
            p[2] = wmma::__float_to_tf32(v.z);
            p[3] = wmma::__float_to_tf32(v.w);
        }
        __syncthreads();
#pragma unroll
        for (int kk = 0; kk < 32; kk += 8) {
            wmma::fragment<wmma::matrix_a, 16, 16, 8, wmma::precision::tf32, wmma::row_major> a0, a1;
            wmma::fragment<wmma::matrix_b, 16, 16, 8, wmma::precision::tf32, wmma::row_major> b0, b1;
            wmma::load_matrix_sync(a0, As + wr * 36 + kk, 36);
            wmma::load_matrix_sync(a1, As + (wr + 16) * 36 + kk, 36);
            wmma::load_matrix_sync(b0, Bs + kk * 68 + wc, 68);
            wmma::load_matrix_sync(b1, Bs + kk * 68 + wc + 16, 68);
            wmma::mma_sync(c[0][0], a0, b0, c[0][0]);
            wmma::mma_sync(c[0][1], a0, b1, c[0][1]);
            wmma::mma_sync(c[1][0], a1, b0, c[1][0]);
            wmma::mma_sync(c[1][1], a1, b1, c[1][1]);
        }
        __syncthreads();
    }

    // stage C tile (aliases As/Bs, safe after sync)
#pragma unroll
    for (int i = 0; i < 2; i++)
#pragma unroll
        for (int j = 0; j < 2; j++)
            wmma::store_matrix_sync(&Cs[wr + i * 16][wc + j * 16], c[i][j], 68, wmma::mem_row_major);
    __syncthreads();

    // write C
    for (int idx = tid; idx < 128 * 64; idx += 256) {
        int m = idx >> 6, nn = idx & 63;
        if (row0 + m < M) C[(size_t)(row0 + m) * N + col0 + nn] = Cs[m][nn];
    }

    // fused alpha: 2 threads per row, 32 cols each
    {
        int r = tid >> 1;
        int half = tid & 1;
        float ps = 0.f, pd = 0.f;
#pragma unroll
        for (int cc = 0; cc < 32; cc++) {
            float v = Cs[r][half * 32 + cc];
            ps = fmaf(v, aS[col0 + half * 32 + cc], ps);
            pd = fmaf(v, aD[col0 + half * 32 + cc], pd);
        }
        ps += __shfl_down_sync(0xffffffffu, ps, 1);
        pd += __shfl_down_sync(0xffffffffu, pd, 1);
        if (half == 0 && row0 + r < M) {
            int nh = N >> 6;
            int head = col0 >> 6;
            gas[(row0 + r) * nh + head] = ps;
            gad[(row0 + r) * nh + head] = pd;
        }
    }
}

// ---------------- per-edge weight precompute (warp per node) -------------------
__global__ __launch_bounds__(256) void k_wprep4(
    const float* __restrict__ as, const float* __restrict__ ad, int n)
{
    int warp = threadIdx.x >> 5, lane = threadIdx.x & 31;
    int node = blockIdx.x * 8 + warp;
    if (node >= n) return;
    int beg = g_off[node];
    int deg = g_off[node + 1] - beg;
    float4 adv = *(const float4*)(ad + node * 4);

    float m0 = -1e30f, m1 = -1e30f, m2 = -1e30f, m3 = -1e30f;
    for (int i = lane; i < deg; i += 32) {
        int s = g_srcs[beg + i];
        float4 av = *(const float4*)(as + s * 4);
        m0 = fmaxf(m0, lrelu(av.x + adv.x));
        m1 = fmaxf(m1, lrelu(av.y + adv.y));
        m2 = fmaxf(m2, lrelu(av.z + adv.z));
        m3 = fmaxf(m3, lrelu(av.w + adv.w));
    }
#pragma unroll
    for (int o = 16; o > 0; o >>= 1) {
        m0 = fmaxf(m0, __shfl_xor_sync(0xffffffffu, m0, o));
        m1 = fmaxf(m1, __shfl_xor_sync(0xffffffffu, m1, o));
        m2 = fmaxf(m2, __shfl_xor_sync(0xffffffffu, m2, o));
        m3 = fmaxf(m3, __shfl_xor_sync(0xffffffffu, m3, o));
    }
    float d0 = 0, d1 = 0, d2 = 0, d3 = 0;
    for (int i = lane; i < deg; i += 32) {
        int s = g_srcs[beg + i];
        float4 av = *(const float4*)(as + s * 4);
        float w0 = __expf(lrelu(av.x + adv.x) - m0);
        float w1 = __expf(lrelu(av.y + adv.y) - m1);
        float w2 = __expf(lrelu(av.z + adv.z) - m2);
        float w3 = __expf(lrelu(av.w + adv.w) - m3);
        *(float4*)(g_w + (size_t)(beg + i) * 4) = make_float4(w0, w1, w2, w3);
        d0 += w0; d1 += w1; d2 += w2; d3 += w3;
    }
#pragma unroll
    for (int o = 16; o > 0; o >>= 1) {
        d0 += __shfl_xor_sync(0xffffffffu, d0, o);
        d1 += __shfl_xor_sync(0xffffffffu, d1, o);
        d2 += __shfl_xor_sync(0xffffffffu, d2, o);
        d3 += __shfl_xor_sync(0xffffffffu, d3, o);
    }
    float r0 = 1.f / (d0 + 1e-16f);
    float r1 = 1.f / (d1 + 1e-16f);
    float r2 = 1.f / (d2 + 1e-16f);
    float r3 = 1.f / (d3 + 1e-16f);
    for (int i = lane; i < deg; i += 32) {
        float4 w = *(const float4*)(g_w + (size_t)(beg + i) * 4);
        w.x *= r0; w.y *= r1; w.z *= r2; w.w *= r3;
        *(float4*)(g_w + (size_t)(beg + i) * 4) = w;
    }
}

__global__ __launch_bounds__(256) void k_wprep1(
    const float* __restrict__ as, const float* __restrict__ ad, int n)
{
    int warp = threadIdx.x >> 5, lane = threadIdx.x & 31;
    int node = blockIdx.x * 8 + warp;
    if (node >= n) return;
    int beg = g_off[node];
    int deg = g_off[node + 1] - beg;
    float adv = ad[node];

    float m = -1e30f;
    for (int i = lane; i < deg; i += 32)
        m = fmaxf(m, lrelu(as[g_srcs[beg + i]] + adv));
#pragma unroll
    for (int o = 16; o > 0; o >>= 1)
        m = fmaxf(m, __shfl_xor_sync(0xffffffffu, m, o));
    float d = 0.f;
    for (int i = lane; i < deg; i += 32) {
        float w = __expf(lrelu(as[g_srcs[beg + i]] + adv) - m);
        g_w[beg + i] = w;
        d += w;
    }
#pragma unroll
    for (int o = 16; o > 0; o >>= 1)
        d += __shfl_xor_sync(0xffffffffu, d, o);
    float r = 1.f / (d + 1e-16f);
    for (int i = lane; i < deg; i += 32)
        g_w[beg + i] *= r;
}

// ---------------- GAT aggregation, H=4: 1 node/block, 256 thr, float4 ----------
__global__ __launch_bounds__(256) void k_agg4(
    const float* __restrict__ h, const float* __restrict__ bias,
    float* __restrict__ out, int elu)
{
    __shared__ float4 red[256];
    int n = blockIdx.x, tid = threadIdx.x;
    int sub = tid >> 6;           // edge subgroup 0..3
    int l   = tid & 63;           // feature quad: features 4l..4l+3
    int head = l >> 4;
    int beg = g_off[n];
    int deg = g_off[n + 1] - beg;

    float4 acc = make_float4(0.f, 0.f, 0.f, 0.f);
    int i = sub;
    for (; i + 4 < deg; i += 8) {
        int s0 = g_srcs[beg + i];
        int s1 = g_srcs[beg + i + 4];
        float w0 = g_w[(size_t)(beg + i) * 4 + head];
        float w1 = g_w[(size_t)(beg + i + 4) * 4 + head];
        float4 v0 = *(const float4*)&h[(size_t)s0 * 256 + l * 4];
        float4 v1 = *(const float4*)&h[(size_t)s1 * 256 + l * 4];
        acc.x = fmaf(v0.x, w0, acc.x); acc.y = fmaf(v0.y, w0, acc.y);
        acc.z = fmaf(v0.z, w0, acc.z); acc.w = fmaf(v0.w, w0, acc.w);
        acc.x = fmaf(v1.x, w1, acc.x); acc.y = fmaf(v1.y, w1, acc.y);
        acc.z = fmaf(v1.z, w1, acc.z); acc.w = fmaf(v1.w, w1, acc.w);
    }
    if (i < deg) {
        int s = g_srcs[beg + i];
        float w = g_w[(size_t)(beg + i) * 4 + head];
        float4 v = *(const float4*)&h[(size_t)s * 256 + l * 4];
        acc.x = fmaf(v.x, w, acc.x); acc.y = fmaf(v.y, w, acc.y);
        acc.z = fmaf(v.z, w, acc.z); acc.w = fmaf(v.w, w, acc.w);
    }

    red[tid] = acc;
    __syncthreads();
    if (sub == 0) {
        float4 a1 = red[l + 64], a2 = red[l + 128], a3 = red[l + 192];
        acc.x += a1.x + a2.x + a3.x;
        acc.y += a1.y + a2.y + a3.y;
        acc.z += a1.z + a2.z + a3.z;
        acc.w += a1.w + a2.w + a3.w;
        float4 b = *(const float4*)&bias[l * 4];
        acc.x += b.x; acc.y += b.y; acc.z += b.z; acc.w += b.w;
        if (elu) {
            acc.x = acc.x > 0.f ? acc.x : expm1f(acc.x);
            acc.y = acc.y > 0.f ? acc.y : expm1f(acc.y);
            acc.z = acc.z > 0.f ? acc.z : expm1f(acc.z);
            acc.w = acc.w > 0.f ? acc.w : expm1f(acc.w);
        }
        *(float4*)&out[(size_t)n * 256 + l * 4] = acc;
    }
}

// ---------------- GAT aggregation, H=1, F=64 -----------------------------------
__global__ __launch_bounds__(64) void k_agg1(
    const float* __restrict__ h, const float* __restrict__ bias,
    float* __restrict__ out)
{
    int n = blockIdx.x, f = threadIdx.x;
    int beg = g_off[n];
    int deg = g_off[n + 1] - beg;

    float acc = 0.f;
    int i = 0;
    for (; i + 4 <= deg; i += 4) {
        int s0 = g_srcs[beg + i + 0];
        int s1 = g_srcs[beg + i + 1];
        int s2 = g_srcs[beg + i + 2];
        int s3 = g_srcs[beg + i + 3];
        float w0 = g_w[beg + i + 0];
        float w1 = g_w[beg + i + 1];
        float w2 = g_w[beg + i + 2];
        float w3 = g_w[beg + i + 3];
        acc = fmaf(h[(size_t)s0 * 64 + f], w0, acc);
        acc = fmaf(h[(size_t)s1 * 64 + f], w1, acc);
        acc = fmaf(h[(size_t)s2 * 64 + f], w2, acc);
        acc = fmaf(h[(size_t)s3 * 64 + f], w3, acc);
    }
    for (; i < deg; i++)
        acc = fmaf(h[(size_t)g_srcs[beg + i] * 64 + f], g_w[beg + i], acc);
    out[(size_t)n * 64 + f] = acc + bias[f];
}

// ---------------- mean pool over sorted batch ids -----------------------------
__global__ void k_pool(const float* __restrict__ node, const int* __restrict__ batch,
                       float* __restrict__ gout, int n)
{
    int g = blockIdx.x;
    int lo = 0, hi = n;
    while (lo < hi) { int mid = (lo + hi) >> 1; if (batch[mid] < g) lo = mid + 1; else hi = mid; }
    int start = lo;
    lo = start; hi = n;
    while (lo < hi) { int mid = (lo + hi) >> 1; if (batch[mid] < g + 1) lo = mid + 1; else hi = mid; }
    int end = lo;

    int f = threadIdx.x & 63;
    int sub = threadIdx.x >> 6;
    float acc = 0.f;
    for (int i = start + sub; i < end; i += 4)
        acc += node[(size_t)i * 64 + f];
    __shared__ float s[256];
    s[threadIdx.x] = acc;
    __syncthreads();
    if (threadIdx.x < 64) {
        float v = s[threadIdx.x] + s[threadIdx.x + 64] + s[threadIdx.x + 128] + s[threadIdx.x + 192];
        int cnt = end - start;
        gout[g * 64 + threadIdx.x] = v / (float)max(cnt, 1);
    }
}

// ---------------- host side ----------------------------------------------------
extern "C" void kernel_launch(void* const* d_in, const int* in_sizes, int n_in,
                              void* d_out, int out_size)
{
    const float* x    = (const float*)d_in[0];
    const int*   ei   = (const int*)d_in[1];
    const int*   batch= (const int*)d_in[2];
    const float* W1   = (const float*)d_in[3];
    const float* as1  = (const float*)d_in[4];
    const float* ad1  = (const float*)d_in[5];
    const float* b1   = (const float*)d_in[6];
    const float* W2   = (const float*)d_in[7];
    const float* as2  = (const float*)d_in[8];
    const float* ad2  = (const float*)d_in[9];
    const float* b2   = (const float*)d_in[10];
    const float* W3   = (const float*)d_in[11];
    const float* as3  = (const float*)d_in[12];
    const float* ad3  = (const float*)d_in[13];
    const float* b3   = (const float*)d_in[14];

    int n = in_sizes[0] / 256;
    int E = in_sizes[1] / 2;
    float* out = (float*)d_out;
    int G = (out_size - n * 64) / 64;

    float *p_h, *p_h2, *p_as, *p_ad;
    cudaGetSymbolAddress((void**)&p_h,  g_h);
    cudaGetSymbolAddress((void**)&p_h2, g_h2);
    cudaGetSymbolAddress((void**)&p_as, g_as);
    cudaGetSymbolAddress((void**)&p_ad, g_ad);

    int tot = E + n;
    int nb = (n + 1023) / 1024;
    int nw = (n + 7) / 8;

    dim3 gbig(4, (n + 127) / 128);
    dim3 gsm(1, (n + 127) / 128);

    // Launch index 3 = layer-1 GEMM so ncu (which profiles launch #3) shows it.
    k_zero<<<(n + 255) / 256, 256>>>(n);                                        // 0
    k_deg<<<(tot + 255) / 256, 256>>>(ei, E, n);                                // 1
    k_part<<<nb, 1024>>>(n);                                                    // 2
    k_gemm_tc<<<gbig, 256>>>(x, W1, p_h2, as1, ad1, p_as, p_ad, n, 256, 256);   // 3
    k_scanp<<<1, 64>>>(nb);                                                     // 4
    k_offsets<<<nb, 1024>>>(n);                                                 // 5
    k_scatter<<<(tot + 255) / 256, 256>>>(ei, E, n);                            // 6

    // layer 1 (cont.)
    k_wprep4<<<nw, 256>>>(p_as, p_ad, n);
    k_agg4<<<n, 256>>>(p_h2, b1, p_h, 1);
    // layer 2
    k_gemm_tc<<<gbig, 256>>>(p_h, W2, p_h2, as2, ad2, p_as, p_ad, n, 256, 256);
    k_wprep4<<<nw, 256>>>(p_as, p_ad, n);
    k_agg4<<<n, 256>>>(p_h2, b2, p_h, 1);
    // layer 3
    k_gemm_tc<<<gsm, 256>>>(p_h, W3, p_h2, as3, ad3, p_as, p_ad, n, 64, 256);
    k_wprep1<<<nw, 256>>>(p_as, p_ad, n);
    k_agg1<<<n, 64>>>(p_h2, b3, out);
    // pooling
    k_pool<<<G, 256>>>(out, batch, out + n * 64, n);
}